// round 3
// baseline (speedup 1.0000x reference)
#include <cuda_runtime.h>
#include <cuda_bf16.h>
#include <cstdint>

// ============================================================================
// GAT fusion: B=8192, N=12, D=256, output rows SEL={0,3,6,9}.
//
// Math:
//   Wh1 = relu(h@Wv^T+bv); k1 = relu(h@Wk^T+bk)          (full 12 rows)
//   q1  = relu(h_sel@Wq^T+bq)                             (4 rows/batch)
//   s   = q1.k1, adj mask, softmax, * label
//   f1  = att @ Wh1
//   out = f1 @ (Wf@Wo1)^T + (Wf@bo1+bf)                   (folded affine pair)
//
// All GEMMs: bf16x3 split (hi+lo) on mma.sync.m16n8k16 -> fp32-grade accuracy.
// ============================================================================

#define BATCH   8192
#define NNODE   12
#define DIM     256
#define M_VK    (BATCH * NNODE)     // 98304
#define M_SEL   (BATCH * 4)         // 32768

// ---------------- scratch (device globals; no allocation) -------------------
__device__ float g_Wh1[M_VK * DIM];
__device__ float g_k1 [M_VK * DIM];
__device__ float g_q1 [M_SEL * DIM];
__device__ float g_f1 [M_SEL * DIM];
__device__ float g_Wc [DIM * DIM];
__device__ float g_bc [DIM];
__device__ __nv_bfloat16 g_Wv_h[DIM*DIM], g_Wv_l[DIM*DIM];
__device__ __nv_bfloat16 g_Wk_h[DIM*DIM], g_Wk_l[DIM*DIM];
__device__ __nv_bfloat16 g_Wq_h[DIM*DIM], g_Wq_l[DIM*DIM];
__device__ __nv_bfloat16 g_Wc_h[DIM*DIM], g_Wc_l[DIM*DIM];

// ---------------- small helpers ---------------------------------------------
__device__ __forceinline__ uint32_t smem_u32(const void* p) {
    return (uint32_t)__cvta_generic_to_shared(p);
}
__device__ __forceinline__ void ldmatrix_x4(uint32_t& r0, uint32_t& r1,
                                            uint32_t& r2, uint32_t& r3, uint32_t addr) {
    asm volatile("ldmatrix.sync.aligned.m8n8.x4.shared.b16 {%0,%1,%2,%3}, [%4];\n"
                 : "=r"(r0), "=r"(r1), "=r"(r2), "=r"(r3) : "r"(addr));
}
__device__ __forceinline__ void ldmatrix_x2(uint32_t& r0, uint32_t& r1, uint32_t addr) {
    asm volatile("ldmatrix.sync.aligned.m8n8.x2.shared.b16 {%0,%1}, [%2];\n"
                 : "=r"(r0), "=r"(r1) : "r"(addr));
}
__device__ __forceinline__ void mma_bf16(float c[4],
                                         uint32_t a0, uint32_t a1, uint32_t a2, uint32_t a3,
                                         uint32_t b0, uint32_t b1) {
    asm volatile("mma.sync.aligned.m16n8k16.row.col.f32.bf16.bf16.f32 "
                 "{%0,%1,%2,%3}, {%4,%5,%6,%7}, {%8,%9}, {%0,%1,%2,%3};\n"
                 : "+f"(c[0]), "+f"(c[1]), "+f"(c[2]), "+f"(c[3])
                 : "r"(a0), "r"(a1), "r"(a2), "r"(a3), "r"(b0), "r"(b1));
}

// ---------------- weight split: fp32 -> (hi, lo) bf16 -----------------------
__global__ void convert_w_kernel(const float* __restrict__ src,
                                 __nv_bfloat16* __restrict__ hi,
                                 __nv_bfloat16* __restrict__ lo) {
    int i = blockIdx.x * 256 + threadIdx.x;          // grid covers 65536 exactly
    float x = src[i];
    __nv_bfloat16 h = __float2bfloat16(x);
    hi[i] = h;
    lo[i] = __float2bfloat16(x - __bfloat162float(h));
}

// ---------------- fold: Wc = Wf@Wo1, bc = Wf@bo1+bf --------------------------
__global__ void fold_kernel(const float* __restrict__ Wf, const float* __restrict__ Wo1,
                            const float* __restrict__ bo1, const float* __restrict__ bf,
                            float* __restrict__ Wc, float* __restrict__ bc) {
    int o = blockIdx.x, d = threadIdx.x;
    float acc = 0.f;
    #pragma unroll 8
    for (int h = 0; h < 256; ++h) acc = fmaf(Wf[o * 256 + h], Wo1[h * 256 + d], acc);
    Wc[o * 256 + d] = acc;
    if (d == 0) {
        float a2 = 0.f;
        for (int h = 0; h < 256; ++h) a2 = fmaf(Wf[o * 256 + h], bo1[h], a2);
        bc[o] = a2 + bf[o];
    }
}

// ---------------- main GEMM: C = act(A @ W^T + b), bf16x3 --------------------
// A: [M,256] fp32 (optionally row-gathered: gm -> (gm>>2)*12 + 3*(gm&3))
// W given pre-split as hi/lo bf16 [256(out),256(in)] row-major.
// Block = 256 thr, tile 128(M) x 128(N) x 32(K). DUAL: blockIdx.y 0,1 -> set0
// cols 0/128; 2,3 -> set1 (second weight/out).
#define LDS_P 40   // bf16 row stride in smem (80B: 16B-aligned, ldmatrix conflict-free)

template<bool GATHER, bool RELU, bool DUAL>
__global__ void __launch_bounds__(256, 2)
gemm_kernel(const float* __restrict__ A,
            const __nv_bfloat16* __restrict__ W0h, const __nv_bfloat16* __restrict__ W0l,
            const float* __restrict__ bias0, float* __restrict__ C0,
            const __nv_bfloat16* __restrict__ W1h, const __nv_bfloat16* __restrict__ W1l,
            const float* __restrict__ bias1, float* __restrict__ C1) {
    __shared__ __nv_bfloat16 sAh[128 * LDS_P];
    __shared__ __nv_bfloat16 sAl[128 * LDS_P];
    __shared__ __nv_bfloat16 sBh[128 * LDS_P];
    __shared__ __nv_bfloat16 sBl[128 * LDS_P];

    const int t = threadIdx.x;

    const __nv_bfloat16 *Wh, *Wl;
    const float* bias;
    float* C;
    int ncol0;
    if constexpr (DUAL) {
        int y = blockIdx.y;
        if (y < 2) { Wh = W0h; Wl = W0l; bias = bias0; C = C0; }
        else       { Wh = W1h; Wl = W1l; bias = bias1; C = C1; }
        ncol0 = (y & 1) * 128;
    } else {
        Wh = W0h; Wl = W0l; bias = bias0; C = C0;
        ncol0 = blockIdx.y * 128;
    }

    // ---- per-thread load mapping (thread t: smem row t>>1, 16-col segment) --
    const int lrow = t >> 1;
    const int lseg = (t & 1) * 16;
    int grow = blockIdx.x * 128 + lrow;
    if constexpr (GATHER) grow = (grow >> 2) * 12 + 3 * (grow & 3);
    const float* aptr = A + grow * 256 + lseg;
    const __nv_bfloat16* bhptr = Wh + (ncol0 + lrow) * 256 + lseg;
    const __nv_bfloat16* blptr = Wl + (ncol0 + lrow) * 256 + lseg;
    __nv_bfloat16* sa_h = &sAh[lrow * LDS_P + lseg];
    __nv_bfloat16* sa_l = &sAl[lrow * LDS_P + lseg];
    __nv_bfloat16* sb_h = &sBh[lrow * LDS_P + lseg];
    __nv_bfloat16* sb_l = &sBl[lrow * LDS_P + lseg];

    // ---- fragment addressing ------------------------------------------------
    const int lane = t & 31, wid = t >> 5;
    const int wm = (wid & 1) * 64;        // 2 warps in M
    const int wn = (wid >> 1) * 32;       // 4 warps in N
    const uint32_t base_ah = smem_u32(sAh), base_al = smem_u32(sAl);
    const uint32_t base_bh = smem_u32(sBh), base_bl = smem_u32(sBl);
    const uint32_t aoff = ((wm + (lane & 15)) * LDS_P + ((lane >> 4) << 3)) * 2;
    const uint32_t boff = (((lane & 7)) * LDS_P + (((lane >> 3) & 1) << 3)) * 2;

    float c[4][4][4];
    #pragma unroll
    for (int i = 0; i < 4; ++i)
        #pragma unroll
        for (int j = 0; j < 4; ++j)
            { c[i][j][0] = 0.f; c[i][j][1] = 0.f; c[i][j][2] = 0.f; c[i][j][3] = 0.f; }

    float4 af[4];

#define LD_A(kt) {                                                     \
        const float4* p = (const float4*)(aptr + (kt) * 32);           \
        af[0] = p[0]; af[1] = p[1]; af[2] = p[2]; af[3] = p[3]; }

#define STS_A() {                                                      \
        const float* xf = (const float*)af;                            \
        uint32_t hw[8], lw[8];                                         \
        _Pragma("unroll")                                              \
        for (int e = 0; e < 8; ++e) {                                  \
            float x0 = xf[2*e], x1 = xf[2*e+1];                        \
            __nv_bfloat16 h0 = __float2bfloat16(x0);                   \
            __nv_bfloat16 h1 = __float2bfloat16(x1);                   \
            float r0 = x0 - __bfloat162float(h0);                      \
            float r1 = x1 - __bfloat162float(h1);                      \
            __nv_bfloat16 l0 = __float2bfloat16(r0);                   \
            __nv_bfloat16 l1 = __float2bfloat16(r1);                   \
            hw[e] = (uint32_t)__bfloat16_as_ushort(h0) |               \
                    ((uint32_t)__bfloat16_as_ushort(h1) << 16);        \
            lw[e] = (uint32_t)__bfloat16_as_ushort(l0) |               \
                    ((uint32_t)__bfloat16_as_ushort(l1) << 16);        \
        }                                                              \
        ((uint4*)sa_h)[0] = make_uint4(hw[0], hw[1], hw[2], hw[3]);    \
        ((uint4*)sa_h)[1] = make_uint4(hw[4], hw[5], hw[6], hw[7]);    \
        ((uint4*)sa_l)[0] = make_uint4(lw[0], lw[1], lw[2], lw[3]);    \
        ((uint4*)sa_l)[1] = make_uint4(lw[4], lw[5], lw[6], lw[7]); }

#define LDSTS_B(kt) {                                                  \
        const uint4* ph = (const uint4*)(bhptr + (kt) * 32);           \
        const uint4* pl = (const uint4*)(blptr + (kt) * 32);           \
        uint4 h0 = ph[0], h1 = ph[1];                                  \
        uint4 l0 = pl[0], l1 = pl[1];                                  \
        ((uint4*)sb_h)[0] = h0; ((uint4*)sb_h)[1] = h1;                \
        ((uint4*)sb_l)[0] = l0; ((uint4*)sb_l)[1] = l1; }

    LD_A(0); STS_A(); LDSTS_B(0);
    __syncthreads();

    #pragma unroll 1
    for (int kt = 0; kt < 8; ++kt) {
        if (kt < 7) LD_A(kt + 1);      // LDG issued before compute (latency hidden)

        #pragma unroll
        for (int ks = 0; ks < 32; ks += 16) {
            uint32_t rbh[4][2], rbl[4][2];
            #pragma unroll
            for (int j = 0; j < 4; ++j) {
                uint32_t o = boff + (uint32_t)(((wn + 8 * j) * LDS_P + ks) * 2);
                ldmatrix_x2(rbh[j][0], rbh[j][1], base_bh + o);
                ldmatrix_x2(rbl[j][0], rbl[j][1], base_bl + o);
            }
            #pragma unroll
            for (int i = 0; i < 4; ++i) {
                uint32_t o = aoff + (uint32_t)((i * 16 * LDS_P + ks) * 2);
                uint32_t ah0, ah1, ah2, ah3, al0, al1, al2, al3;
                ldmatrix_x4(ah0, ah1, ah2, ah3, base_ah + o);
                ldmatrix_x4(al0, al1, al2, al3, base_al + o);
                #pragma unroll
                for (int j = 0; j < 4; ++j) {
                    mma_bf16(c[i][j], ah0, ah1, ah2, ah3, rbh[j][0], rbh[j][1]);
                    mma_bf16(c[i][j], ah0, ah1, ah2, ah3, rbl[j][0], rbl[j][1]);
                    mma_bf16(c[i][j], al0, al1, al2, al3, rbh[j][0], rbh[j][1]);
                }
            }
        }
        __syncthreads();
        if (kt < 7) {
            LDSTS_B(kt + 1);
            STS_A();
            __syncthreads();
        }
    }

    // ---- epilogue -----------------------------------------------------------
    const int gr = lane >> 2, gc = (lane & 3) * 2;
    const int mbase = blockIdx.x * 128 + wm;
    #pragma unroll
    for (int i = 0; i < 4; ++i) {
        #pragma unroll
        for (int j = 0; j < 4; ++j) {
            int col = ncol0 + wn + 8 * j + gc;
            float b0v = bias[col], b1v = bias[col + 1];
            float v0 = c[i][j][0] + b0v, v1 = c[i][j][1] + b1v;
            float v2 = c[i][j][2] + b0v, v3 = c[i][j][3] + b1v;
            if (RELU) {
                v0 = fmaxf(v0, 0.f); v1 = fmaxf(v1, 0.f);
                v2 = fmaxf(v2, 0.f); v3 = fmaxf(v3, 0.f);
            }
            int r0 = mbase + 16 * i + gr;
            *(float2*)&C[r0 * 256 + col]        = make_float2(v0, v1);
            *(float2*)&C[(r0 + 8) * 256 + col]  = make_float2(v2, v3);
        }
    }
#undef LD_A
#undef STS_A
#undef LDSTS_B
}

// ---------------- attention: scores -> softmax -> label -> aggregate ---------
// block = 128 thr = one batch b; warp w handles sel row i=w (node 3w).
__global__ void __launch_bounds__(128)
attn_kernel(const float* __restrict__ q1, const float* __restrict__ k1,
            const float* __restrict__ wh1, const float* __restrict__ label,
            const float* __restrict__ adj, float* __restrict__ f1) {
    __shared__ float sk [NNODE * 256];
    __shared__ float swh[NNODE * 256];
    __shared__ float sq [4 * 256];
    __shared__ float sadj[4 * NNODE];
    __shared__ float slab[NNODE];

    const int b = blockIdx.x, t = threadIdx.x;

    const float4* k4 = (const float4*)(k1  + b * NNODE * 256);
    const float4* w4 = (const float4*)(wh1 + b * NNODE * 256);
    const float4* q4 = (const float4*)(q1  + b * 4 * 256);
    float4* dk = (float4*)sk;
    float4* dw = (float4*)swh;
    float4* dq = (float4*)sq;
    #pragma unroll
    for (int u = 0; u < 6; ++u) { dk[t + 128 * u] = k4[t + 128 * u];
                                  dw[t + 128 * u] = w4[t + 128 * u]; }
    #pragma unroll
    for (int u = 0; u < 2; ++u)   dq[t + 128 * u] = q4[t + 128 * u];
    if (t < NNODE) slab[t] = label[b * NNODE + t];
    if (t < 4 * NNODE) {
        int i = t / NNODE, m = t % NNODE;
        sadj[t] = adj[(3 * i) * NNODE + m];
    }
    __syncthreads();

    const int w = t >> 5, l = t & 31;
    float qv[8];
    {
        const float4* qp = (const float4*)(sq + w * 256 + l * 8);
        float4 a = qp[0], bq_ = qp[1];
        qv[0]=a.x; qv[1]=a.y; qv[2]=a.z; qv[3]=a.w;
        qv[4]=bq_.x; qv[5]=bq_.y; qv[6]=bq_.z; qv[7]=bq_.w;
    }
    float s[NNODE];
    #pragma unroll
    for (int m = 0; m < NNODE; ++m) {
        const float4* kp = (const float4*)(sk + m * 256 + l * 8);
        float4 a = kp[0], bb = kp[1];
        float p = qv[0]*a.x + qv[1]*a.y + qv[2]*a.z + qv[3]*a.w
                + qv[4]*bb.x + qv[5]*bb.y + qv[6]*bb.z + qv[7]*bb.w;
        s[m] = p;
    }
    #pragma unroll
    for (int m = 0; m < NNODE; ++m)
        #pragma unroll
        for (int off = 16; off > 0; off >>= 1)
            s[m] += __shfl_xor_sync(0xffffffffu, s[m], off);

    float mx = -3.0e38f;
    #pragma unroll
    for (int m = 0; m < NNODE; ++m) {
        float sm = (sadj[w * NNODE + m] > 0.5f) ? s[m] : -9.0e15f;
        s[m] = sm;
        mx = fmaxf(mx, sm);
    }
    float sum = 0.f;
    #pragma unroll
    for (int m = 0; m < NNODE; ++m) { float p = expf(s[m] - mx); s[m] = p; sum += p; }
    const float inv = 1.f / sum;
    #pragma unroll
    for (int m = 0; m < NNODE; ++m) s[m] = s[m] * inv * slab[m];

    float o[8] = {0,0,0,0,0,0,0,0};
    #pragma unroll
    for (int m = 0; m < NNODE; ++m) {
        const float4* wp = (const float4*)(swh + m * 256 + l * 8);
        float4 a = wp[0], bb = wp[1];
        float am = s[m];
        o[0] = fmaf(am, a.x, o[0]); o[1] = fmaf(am, a.y, o[1]);
        o[2] = fmaf(am, a.z, o[2]); o[3] = fmaf(am, a.w, o[3]);
        o[4] = fmaf(am, bb.x, o[4]); o[5] = fmaf(am, bb.y, o[5]);
        o[6] = fmaf(am, bb.z, o[6]); o[7] = fmaf(am, bb.w, o[7]);
    }
    float* op = f1 + (b * 4 + w) * 256 + l * 8;
    *(float4*)op       = make_float4(o[0], o[1], o[2], o[3]);
    *(float4*)(op + 4) = make_float4(o[4], o[5], o[6], o[7]);
}

// ---------------- host launch ------------------------------------------------
extern "C" void kernel_launch(void* const* d_in, const int* in_sizes, int n_in,
                              void* d_out, int out_size) {
    const float* h     = (const float*)d_in[0];
    const float* adj   = (const float*)d_in[1];
    const float* label = (const float*)d_in[2];
    const float* Wv    = (const float*)d_in[3];
    const float* bv    = (const float*)d_in[4];
    const float* Wk    = (const float*)d_in[5];
    const float* bk    = (const float*)d_in[6];
    const float* Wq    = (const float*)d_in[7];
    const float* bq    = (const float*)d_in[8];
    const float* Wo1   = (const float*)d_in[9];
    const float* bo1   = (const float*)d_in[10];
    const float* Wf    = (const float*)d_in[11];
    const float* bf    = (const float*)d_in[12];
    float* out = (float*)d_out;

    float *p_Wh1, *p_k1, *p_q1, *p_f1, *p_Wc, *p_bc;
    __nv_bfloat16 *p_Wvh, *p_Wvl, *p_Wkh, *p_Wkl, *p_Wqh, *p_Wql, *p_Wch, *p_Wcl;
    cudaGetSymbolAddress((void**)&p_Wh1, g_Wh1);
    cudaGetSymbolAddress((void**)&p_k1,  g_k1);
    cudaGetSymbolAddress((void**)&p_q1,  g_q1);
    cudaGetSymbolAddress((void**)&p_f1,  g_f1);
    cudaGetSymbolAddress((void**)&p_Wc,  g_Wc);
    cudaGetSymbolAddress((void**)&p_bc,  g_bc);
    cudaGetSymbolAddress((void**)&p_Wvh, g_Wv_h);
    cudaGetSymbolAddress((void**)&p_Wvl, g_Wv_l);
    cudaGetSymbolAddress((void**)&p_Wkh, g_Wk_h);
    cudaGetSymbolAddress((void**)&p_Wkl, g_Wk_l);
    cudaGetSymbolAddress((void**)&p_Wqh, g_Wq_h);
    cudaGetSymbolAddress((void**)&p_Wql, g_Wq_l);
    cudaGetSymbolAddress((void**)&p_Wch, g_Wc_h);
    cudaGetSymbolAddress((void**)&p_Wcl, g_Wc_l);

    convert_w_kernel<<<256, 256>>>(Wv, p_Wvh, p_Wvl);
    convert_w_kernel<<<256, 256>>>(Wk, p_Wkh, p_Wkl);
    convert_w_kernel<<<256, 256>>>(Wq, p_Wqh, p_Wql);
    fold_kernel<<<256, 256>>>(Wf, Wo1, bo1, bf, p_Wc, p_bc);
    convert_w_kernel<<<256, 256>>>(p_Wc, p_Wch, p_Wcl);

    // V+K fused GEMM over h: M=98304, dual 256-col outputs
    gemm_kernel<false, true, true><<<dim3(M_VK / 128, 4), 256>>>(
        h, p_Wvh, p_Wvl, bv, p_Wh1, p_Wkh, p_Wkl, bk, p_k1);

    // Q GEMM over gathered sel rows: M=32768
    gemm_kernel<true, true, false><<<dim3(M_SEL / 128, 2), 256>>>(
        h, p_Wqh, p_Wql, bq, p_q1, nullptr, nullptr, nullptr, nullptr);

    // attention + aggregation
    attn_kernel<<<BATCH, 128>>>(p_q1, p_k1, p_Wh1, label, adj, p_f1);

    // folded output GEMM straight into d_out: M=32768
    gemm_kernel<false, false, false><<<dim3(M_SEL / 128, 2), 256>>>(
        p_f1, p_Wch, p_Wcl, p_bc, out, nullptr, nullptr, nullptr, nullptr);
}